// round 11
// baseline (speedup 1.0000x reference)
#include <cuda_runtime.h>
#include <cuda_bf16.h>

#define D 64
#define MAXN 100032
#define MAXE 1600000
#define NEG_SLOPE 0.2f
#define CHUNK 16
#define RPAD 36   // padded row stride (floats): 144B keeps LDS.128 conflict-free

// ---------------- scratch (static device memory; no allocs allowed) -------------
__device__ float4 g_Q[64 * 32];   // Q[r][l] = (Pt[2l], Pt[2l+1], Pb[2l], Pb[2l+1])
__device__ int   g_is64;          // 1 if edge arrays are int64, 0 if int32
__device__ int   g_deg[MAXN];
__device__ int   g_ptr[MAXN + 1];
__device__ int   g_cur[MAXN];
__device__ int   g_bsum[256];
__device__ int   g_packed[MAXE];  // (rel<<20) | tail
__device__ float g_embA[MAXN * D];

// ---------------- helpers ----------------
__device__ __forceinline__ float warp_sum(float v) {
    v += __shfl_xor_sync(0xffffffffu, v, 16);
    v += __shfl_xor_sync(0xffffffffu, v, 8);
    v += __shfl_xor_sync(0xffffffffu, v, 4);
    v += __shfl_xor_sync(0xffffffffu, v, 2);
    v += __shfl_xor_sync(0xffffffffu, v, 1);
    return v;
}

__device__ __forceinline__ int load_idx(const void* base, long long i, int is64) {
    if (is64) return (int)((const long long*)base)[i];
    return ((const int*)base)[i];
}

// ---------------- fused init: zero deg + precompute P + dtype detect ------------
// blocks 0..63: P rows for relation r=blockIdx; block 64: dtype detection.
// all blocks also strided-zero g_deg.
__global__ void k_init(const float* __restrict__ W, const float* __restrict__ rel,
                       const unsigned int* __restrict__ ew, int N) {
    int b = blockIdx.x, t = threadIdx.x;
    // zero g_deg cooperatively
    for (int i = b * 128 + t; i < N; i += 65 * 128) g_deg[i] = 0;

    if (b < 64) {
        // P[r][j] = sum_d W[j][d] * rel[r][d], packed into float4 table
        int j = t;  // 0..127
        const float* wrow = W + j * D;
        const float* rrow = rel + b * D;
        float s = 0.f;
#pragma unroll
        for (int d = 0; d < D; d++) s += wrow[d] * rrow[d];
        int jj   = (j < 64) ? j : (j - 64);
        int lane = jj >> 1;
        int comp = (jj & 1) + ((j < 64) ? 0 : 2);
        ((float*)&g_Q[b * 32 + lane])[comp] = s;
    } else if (t < 32) {
        // int64 LE values < 2^32 have all odd 32-bit words zero; int32 heads don't.
        unsigned int a = ew[2 * t + 1];
        unsigned int c = ew[2 * (t + 32) + 1];
        unsigned int nz = __ballot_sync(0xffffffffu, (a | c) != 0u);
        if (t == 0) g_is64 = (nz == 0u) ? 1 : 0;
    }
}

// ---------------- CSR build ----------------
__global__ void k_hist(const void* __restrict__ ei, int E) {
    int e = blockIdx.x * blockDim.x + threadIdx.x;
    if (e >= E) return;
    int head = load_idx(ei, e, g_is64);
    atomicAdd(&g_deg[head], 1);
}

// warp-shfl block scan (exclusive to g_ptr, block total to g_bsum)
__global__ void k_scan1(int n) {
    __shared__ int wsum[32];
    int i = blockIdx.x * 1024 + threadIdx.x;
    int lane = threadIdx.x & 31, wid = threadIdx.x >> 5;
    int v = (i < n) ? g_deg[i] : 0;
    int sc = v;
#pragma unroll
    for (int off = 1; off < 32; off <<= 1) {
        int t = __shfl_up_sync(0xffffffffu, sc, off);
        if (lane >= off) sc += t;
    }
    if (lane == 31) wsum[wid] = sc;
    __syncthreads();
    if (wid == 0) {
        int w = wsum[lane];
#pragma unroll
        for (int off = 1; off < 32; off <<= 1) {
            int t = __shfl_up_sync(0xffffffffu, w, off);
            if (lane >= off) w += t;
        }
        wsum[lane] = w;
    }
    __syncthreads();
    int incl = sc + ((wid > 0) ? wsum[wid - 1] : 0);
    if (i < n) g_ptr[i] = incl - v;   // exclusive
    if (threadIdx.x == 1023) g_bsum[blockIdx.x] = incl;
}

// parallel scan of block sums (nb <= 256), exclusive in-place
__global__ void k_scan2(int nb) {
    __shared__ int wsum[8];
    int t = threadIdx.x, lane = t & 31, wid = t >> 5;
    int v = (t < nb) ? g_bsum[t] : 0;
    int sc = v;
#pragma unroll
    for (int off = 1; off < 32; off <<= 1) {
        int x = __shfl_up_sync(0xffffffffu, sc, off);
        if (lane >= off) sc += x;
    }
    if (lane == 31) wsum[wid] = sc;
    __syncthreads();
    if (wid == 0 && lane < 8) {
        int w = wsum[lane];
#pragma unroll
        for (int off = 1; off < 8; off <<= 1) {
            int x = __shfl_up_sync(0xffu, w, off);
            if (lane >= off) w += x;
        }
        wsum[lane] = w;
    }
    __syncthreads();
    int incl = sc + ((wid > 0) ? wsum[wid - 1] : 0);
    if (t < nb) g_bsum[t] = incl - v;  // exclusive
}

__global__ void k_scan3(int n, int E) {
    int i = blockIdx.x * 1024 + threadIdx.x;
    if (i < n) {
        int p = g_ptr[i] + g_bsum[blockIdx.x];
        g_ptr[i] = p;
        g_cur[i] = p;
    }
    if (i == 0) g_ptr[n] = E;
}

__global__ void k_place(const void* __restrict__ ei,
                        const void* __restrict__ et, int E) {
    int e = blockIdx.x * blockDim.x + threadIdx.x;
    if (e >= E) return;
    int is64 = g_is64;
    int head = load_idx(ei, e, is64);
    int tail = load_idx(ei, (long long)E + e, is64);
    int rt   = load_idx(et, e, is64);
    int pos = atomicAdd(&g_cur[head], 1);
    g_packed[pos] = (rt << 20) | tail;
}

// ---------------- one hop: warp per head node, chunked batch reduction ----------
// FINAL=0: eout[n] = normalized hop output.
// FINAL=1: eout[n] = 0.25*ent[n] + 0.5*ein[n] + normalized hop output  (= res)
template <int FINAL>
__global__ __launch_bounds__(256)
void k_hop(const float* __restrict__ ein, float* __restrict__ eout,
           const float* __restrict__ ent, int N) {
    __shared__ __align__(16) float red[8][CHUNK * RPAD];
    int wslot = threadIdx.x >> 5;
    int warp = (blockIdx.x * blockDim.x + threadIdx.x) >> 5;
    int lane = threadIdx.x & 31;
    if (warp >= N) return;
    float* rd = red[wslot];

    const float2 eh = *(const float2*)(ein + warp * D + 2 * lane);
    int start = g_ptr[warp];
    int end   = g_ptr[warp + 1];

    float  s_lane = 0.f;
    float2 acc = make_float2(0.f, 0.f);

    for (int base = start; base < end; base += CHUNK) {
        int cnt = end - base;
        if (cnt > CHUNK) cnt = CHUNK;
        int pk_l = (lane < cnt) ? g_packed[base + lane] : 0;

        float2 et_r[CHUNK];
        // phase 1: 16 independent gathers + per-lane partials -> smem
#pragma unroll
        for (int j = 0; j < CHUNK; j++) {
            int pk   = __shfl_sync(0xffffffffu, pk_l, j);
            int tail = pk & 0xFFFFF;
            int rt   = pk >> 20;
            float2 et = make_float2(0.f, 0.f);
            float4 q  = make_float4(0.f, 0.f, 0.f, 0.f);
            if (j < cnt) {
                et = *(const float2*)(ein + tail * D + 2 * lane);
                q  = g_Q[rt * 32 + lane];
            }
            et_r[j] = et;
            rd[j * RPAD + lane] = eh.x * q.x + eh.y * q.y + et.x * q.z + et.y * q.w;
        }
        __syncwarp();

        // phase 2: lane j reduces edge j's 32 partials (vectorized LDS.128),
        // then leaky-relu + exp once per edge (not 32x redundantly)
        float w_l = 0.f;
        if (lane < cnt) {
            const float4* row = (const float4*)(rd + lane * RPAD);
            float logit = 0.f;
#pragma unroll
            for (int k = 0; k < 8; k++) {
                float4 p = row[k];
                logit += (p.x + p.y) + (p.z + p.w);
            }
            logit = (logit > 0.f) ? logit : NEG_SLOPE * logit;
            w_l = __expf(logit);   // max-subtraction dropped: exactly equivalent
            s_lane += w_l;
        }
        __syncwarp();

        // phase 3: weighted accumulate against register-resident et tiles
#pragma unroll
        for (int j = 0; j < CHUNK; j++) {
            float w = __shfl_sync(0xffffffffu, w_l, j);
            acc.x += w * et_r[j].x;
            acc.y += w * et_r[j].y;
        }
    }

    float s = warp_sum(s_lane);

    float2 v;
    if (end > start) {
        float inv = 1.f / s;
        v.x = eh.x + acc.x * inv;
        v.y = eh.y + acc.y * inv;
    } else {
        v = eh;                    // agg = 0 for nodes with no out-edges
    }

    // row-wise L2 normalize
    float nrm2 = warp_sum(v.x * v.x + v.y * v.y);
    float nrm  = fmaxf(sqrtf(nrm2), 1e-12f);
    float inv_n = 1.f / nrm;
    v.x *= inv_n;
    v.y *= inv_n;

    if (FINAL) {
        const float2 e0 = *(const float2*)(ent + warp * D + 2 * lane);
        v.x = 0.25f * e0.x + 0.5f * eh.x + v.x;
        v.y = 0.25f * e0.y + 0.5f * eh.y + v.y;
    }
    *(float2*)(eout + warp * D + 2 * lane) = v;
}

// ---------------- launch ----------------
extern "C" void kernel_launch(void* const* d_in, const int* in_sizes, int n_in,
                              void* d_out, int out_size) {
    const void*  ei  = d_in[0];                  // [2, E] int32 or int64
    const void*  et  = d_in[1];                  // [E]    int32 or int64
    const float* ent = (const float*)d_in[2];    // [N, 64]
    const float* rel = (const float*)d_in[3];    // [R, 64]
    const float* W   = (const float*)d_in[4];    // [128, 64]
    float*       res = (float*)d_out;            // [N, 64]

    int E = in_sizes[0] / 2;
    int N = in_sizes[2] / D;

    void* p_embA;
    cudaGetSymbolAddress(&p_embA, g_embA);

    // fused: zero deg + precompute P + dtype detect
    k_init<<<65, 128>>>(W, rel, (const unsigned int*)ei, N);

    // CSR build
    int egrid = (E + 255) / 256;
    k_hist<<<egrid, 256>>>(ei, E);
    int nblk = (N + 1023) / 1024;
    k_scan1<<<nblk, 1024>>>(N);
    k_scan2<<<1, 256>>>(nblk);
    k_scan3<<<nblk, 1024>>>(N, E);
    k_place<<<egrid, 256>>>(ei, et, E);

    // hop 1: ent -> g_embA ; hop 2: g_embA -> res (with fused residual)
    int hgrid = (N + 7) / 8;   // 8 warps per 256-thread block
    k_hop<0><<<hgrid, 256>>>(ent, (float*)p_embA, ent, N);
    k_hop<1><<<hgrid, 256>>>((float*)p_embA, res, ent, N);
}

// round 12
// speedup vs baseline: 1.5279x; 1.5279x over previous
#include <cuda_runtime.h>
#include <cuda_bf16.h>

#define D 64
#define MAXN 100032
#define MAXE 1600000
#define NEG_SLOPE 0.2f

// ---------------- scratch (static device memory; no allocs allowed) -------------
__device__ float4 g_Qt[64 * 16];  // Qt[r][h] = P[r][4h..4h+3]       (top:  eh side)
__device__ float4 g_Qb[64 * 16];  // Qb[r][h] = P[r][64+4h..64+4h+3] (bot:  et side)
__device__ int   g_is64;          // 1 if edge arrays are int64, 0 if int32
__device__ int   g_deg[MAXN];
__device__ int   g_ptr[MAXN + 1];
__device__ int   g_cur[MAXN];
__device__ int   g_bsum[256];
__device__ int   g_packed[MAXE];  // (rel<<20) | tail
__device__ float g_embA[MAXN * D];

// ---------------- helpers ----------------
__device__ __forceinline__ float warp_sum(float v) {
    v += __shfl_xor_sync(0xffffffffu, v, 16);
    v += __shfl_xor_sync(0xffffffffu, v, 8);
    v += __shfl_xor_sync(0xffffffffu, v, 4);
    v += __shfl_xor_sync(0xffffffffu, v, 2);
    v += __shfl_xor_sync(0xffffffffu, v, 1);
    return v;
}

__device__ __forceinline__ int load_idx(const void* base, long long i, int is64) {
    if (is64) return (int)((const long long*)base)[i];
    return ((const int*)base)[i];
}

// ---------------- fused init: zero deg + precompute P + dtype detect ------------
__global__ void k_init(const float* __restrict__ W, const float* __restrict__ rel,
                       const unsigned int* __restrict__ ew, int N) {
    int b = blockIdx.x, t = threadIdx.x;
    for (int i = b * 128 + t; i < N; i += 65 * 128) g_deg[i] = 0;

    if (b < 64) {
        // P[r][j] = sum_d W[j][d] * rel[r][d]
        int j = t;  // 0..127
        const float* wrow = W + j * D;
        const float* rrow = rel + b * D;
        float s = 0.f;
#pragma unroll
        for (int d = 0; d < D; d++) s += wrow[d] * rrow[d];
        if (j < 64) ((float*)&g_Qt[b * 16 + (j >> 2)])[j & 3] = s;
        else { int jj = j - 64; ((float*)&g_Qb[b * 16 + (jj >> 2)])[jj & 3] = s; }
    } else if (t < 32) {
        // int64 LE values < 2^32 have all odd 32-bit words zero; int32 heads don't.
        unsigned int a = ew[2 * t + 1];
        unsigned int c = ew[2 * (t + 32) + 1];
        unsigned int nz = __ballot_sync(0xffffffffu, (a | c) != 0u);
        if (t == 0) g_is64 = (nz == 0u) ? 1 : 0;
    }
}

// ---------------- CSR build ----------------
__global__ void k_hist(const void* __restrict__ ei, int E) {
    int e = blockIdx.x * blockDim.x + threadIdx.x;
    if (e >= E) return;
    int head = load_idx(ei, e, g_is64);
    atomicAdd(&g_deg[head], 1);
}

// warp-shfl block scan (exclusive to g_ptr, block total to g_bsum)
__global__ void k_scan1(int n) {
    __shared__ int wsum[32];
    int i = blockIdx.x * 1024 + threadIdx.x;
    int lane = threadIdx.x & 31, wid = threadIdx.x >> 5;
    int v = (i < n) ? g_deg[i] : 0;
    int sc = v;
#pragma unroll
    for (int off = 1; off < 32; off <<= 1) {
        int t = __shfl_up_sync(0xffffffffu, sc, off);
        if (lane >= off) sc += t;
    }
    if (lane == 31) wsum[wid] = sc;
    __syncthreads();
    if (wid == 0) {
        int w = wsum[lane];
#pragma unroll
        for (int off = 1; off < 32; off <<= 1) {
            int t = __shfl_up_sync(0xffffffffu, w, off);
            if (lane >= off) w += t;
        }
        wsum[lane] = w;
    }
    __syncthreads();
    int incl = sc + ((wid > 0) ? wsum[wid - 1] : 0);
    if (i < n) g_ptr[i] = incl - v;   // exclusive
    if (threadIdx.x == 1023) g_bsum[blockIdx.x] = incl;
}

// parallel scan of block sums (nb <= 256), exclusive in-place
__global__ void k_scan2(int nb) {
    __shared__ int wsum[8];
    int t = threadIdx.x, lane = t & 31, wid = t >> 5;
    int v = (t < nb) ? g_bsum[t] : 0;
    int sc = v;
#pragma unroll
    for (int off = 1; off < 32; off <<= 1) {
        int x = __shfl_up_sync(0xffffffffu, sc, off);
        if (lane >= off) sc += x;
    }
    if (lane == 31) wsum[wid] = sc;
    __syncthreads();
    if (wid == 0 && lane < 8) {
        int w = wsum[lane];
#pragma unroll
        for (int off = 1; off < 8; off <<= 1) {
            int x = __shfl_up_sync(0xffu, w, off);
            if (lane >= off) w += x;
        }
        wsum[lane] = w;
    }
    __syncthreads();
    int incl = sc + ((wid > 0) ? wsum[wid - 1] : 0);
    if (t < nb) g_bsum[t] = incl - v;  // exclusive
}

__global__ void k_scan3(int n, int E) {
    int i = blockIdx.x * 1024 + threadIdx.x;
    if (i < n) {
        int p = g_ptr[i] + g_bsum[blockIdx.x];
        g_ptr[i] = p;
        g_cur[i] = p;
    }
    if (i == 0) g_ptr[n] = E;
}

__global__ void k_place(const void* __restrict__ ei,
                        const void* __restrict__ et, int E) {
    int e = blockIdx.x * blockDim.x + threadIdx.x;
    if (e >= E) return;
    int is64 = g_is64;
    int head = load_idx(ei, e, is64);
    int tail = load_idx(ei, (long long)E + e, is64);
    int rt   = load_idx(et, e, is64);
    int pos = atomicAdd(&g_cur[head], 1);
    g_packed[pos] = (rt << 20) | tail;
}

// ---------------- one hop: warp per head node, HALF-WARP per edge ---------------
// lanes 0-15 process edge base, lanes 16-31 process edge base+1; each lane owns
// 4 dims (float4). FINAL=0: eout = normalized hop.
// FINAL=1: eout = 0.25*ent + 0.5*ein + normalized hop  (= res)
template <int FINAL>
__global__ __launch_bounds__(256)
void k_hop(const float* __restrict__ ein, float* __restrict__ eout,
           const float* __restrict__ ent, int N) {
    int warp = (blockIdx.x * blockDim.x + threadIdx.x) >> 5;
    int lane = threadIdx.x & 31;
    if (warp >= N) return;
    int half = lane >> 4;      // 0 or 1
    int hl   = lane & 15;      // 0..15: owns dims 4*hl .. 4*hl+3

    const float4 eh = *(const float4*)(ein + warp * D + 4 * hl);
    int start = g_ptr[warp];
    int end   = g_ptr[warp + 1];

    float  s_lane = 0.f;
    float4 acc = make_float4(0.f, 0.f, 0.f, 0.f);

    for (int base = start; base < end; base += 2) {
        int e = base + half;
        bool valid = (e < end);
        int pk = valid ? g_packed[e] : 0;
        int tail = pk & 0xFFFFF;
        int rt   = pk >> 20;

        float4 et = make_float4(0.f, 0.f, 0.f, 0.f);
        float4 qt = make_float4(0.f, 0.f, 0.f, 0.f);
        float4 qb = make_float4(0.f, 0.f, 0.f, 0.f);
        if (valid) {
            et = *(const float4*)(ein + tail * D + 4 * hl);
            qt = g_Qt[rt * 16 + hl];
            qb = g_Qb[rt * 16 + hl];
        }
        float part = eh.x * qt.x + eh.y * qt.y + eh.z * qt.z + eh.w * qt.w
                   + et.x * qb.x + et.y * qb.y + et.z * qb.z + et.w * qb.w;
        // reduce within the 16-lane half (xor 8/4/2/1 never crosses halves)
        part += __shfl_xor_sync(0xffffffffu, part, 8);
        part += __shfl_xor_sync(0xffffffffu, part, 4);
        part += __shfl_xor_sync(0xffffffffu, part, 2);
        part += __shfl_xor_sync(0xffffffffu, part, 1);

        float logit = (part > 0.f) ? part : NEG_SLOPE * part;
        float w = valid ? __expf(logit) : 0.f;  // max-subtraction dropped: exact
        s_lane += w;                            // counted 16x per edge; /16 later
        acc.x += w * et.x;
        acc.y += w * et.y;
        acc.z += w * et.z;
        acc.w += w * et.w;
    }

    // combine the two halves' accumulators
    acc.x += __shfl_xor_sync(0xffffffffu, acc.x, 16);
    acc.y += __shfl_xor_sync(0xffffffffu, acc.y, 16);
    acc.z += __shfl_xor_sync(0xffffffffu, acc.z, 16);
    acc.w += __shfl_xor_sync(0xffffffffu, acc.w, 16);
    float s = warp_sum(s_lane) * (1.f / 16.f);  // exact: /16 is a power of two

    float4 v;
    if (end > start) {
        float inv = 1.f / s;
        v.x = eh.x + acc.x * inv;
        v.y = eh.y + acc.y * inv;
        v.z = eh.z + acc.z * inv;
        v.w = eh.w + acc.w * inv;
    } else {
        v = eh;                    // agg = 0 for nodes with no out-edges
    }

    // row-wise L2 normalize (each dim appears once per half -> /2, exact)
    float nrm2 = warp_sum(v.x * v.x + v.y * v.y + v.z * v.z + v.w * v.w) * 0.5f;
    float nrm  = fmaxf(sqrtf(nrm2), 1e-12f);
    float inv_n = 1.f / nrm;
    v.x *= inv_n; v.y *= inv_n; v.z *= inv_n; v.w *= inv_n;

    if (FINAL) {
        const float4 e0 = *(const float4*)(ent + warp * D + 4 * hl);
        v.x = 0.25f * e0.x + 0.5f * eh.x + v.x;
        v.y = 0.25f * e0.y + 0.5f * eh.y + v.y;
        v.z = 0.25f * e0.z + 0.5f * eh.z + v.z;
        v.w = 0.25f * e0.w + 0.5f * eh.w + v.w;
    }
    if (half == 0)
        *(float4*)(eout + warp * D + 4 * hl) = v;
}

// ---------------- launch ----------------
extern "C" void kernel_launch(void* const* d_in, const int* in_sizes, int n_in,
                              void* d_out, int out_size) {
    const void*  ei  = d_in[0];                  // [2, E] int32 or int64
    const void*  et  = d_in[1];                  // [E]    int32 or int64
    const float* ent = (const float*)d_in[2];    // [N, 64]
    const float* rel = (const float*)d_in[3];    // [R, 64]
    const float* W   = (const float*)d_in[4];    // [128, 64]
    float*       res = (float*)d_out;            // [N, 64]

    int E = in_sizes[0] / 2;
    int N = in_sizes[2] / D;

    void* p_embA;
    cudaGetSymbolAddress(&p_embA, g_embA);

    // fused: zero deg + precompute P + dtype detect
    k_init<<<65, 128>>>(W, rel, (const unsigned int*)ei, N);

    // CSR build
    int egrid = (E + 255) / 256;
    k_hist<<<egrid, 256>>>(ei, E);
    int nblk = (N + 1023) / 1024;
    k_scan1<<<nblk, 1024>>>(N);
    k_scan2<<<1, 256>>>(nblk);
    k_scan3<<<nblk, 1024>>>(N, E);
    k_place<<<egrid, 256>>>(ei, et, E);

    // hop 1: ent -> g_embA ; hop 2: g_embA -> res (with fused residual)
    int hgrid = (N + 7) / 8;   // 8 warps per 256-thread block
    k_hop<0><<<hgrid, 256>>>(ent, (float*)p_embA, ent, N);
    k_hop<1><<<hgrid, 256>>>((float*)p_embA, res, ent, N);
}